// round 14
// baseline (speedup 1.0000x reference)
#include <cuda_runtime.h>
#include <cstdint>

// Problem constants (fixed by setup_inputs)
#define BATCH 4
#define LEN   2048
#define DIM   64
#define KMAX  64

// Byte-Bloom: per group (lo/hi), 2^16 BYTES; k=3 hashes. 128 KB dynamic smem.
#define FBYTES   65536
#define FILT_SMEM (2 * FBYTES)

// Packed sign bits per token: uint2 = (lo d0..31, hi d32..63).
__device__ uint2 g_keys [BATCH * LEN];
__device__ uint2 g_qbits[BATCH * LEN];

__device__ __forceinline__ unsigned hh3(unsigned w) {
    return (w * 0x9E3779B1u) >> 16;          // 16-bit multiplicative hash
}

// ---------------------------------------------------------------------------
// K1: pack sign bits for keys AND queries, and blanket-write the whole output
// with -1.0f (one STG.128 per thread). Output is ~always all -1
// (P(32-bit sign match) = 2^-32); K2 fixes up the statistically-nonexistent
// exceptions afterwards (stream-ordered). 512 blocks x 256 threads:
// 131072 threads x float4 = 2 MB blanket; 4096 warps x 4 tokens = 16384 packs.
// ---------------------------------------------------------------------------
__global__ void __launch_bounds__(256)
pack_blank_kernel(const float* __restrict__ query_up,
                  const float* __restrict__ key_up,
                  float* __restrict__ out) {
    int gtid = blockIdx.x * 256 + threadIdx.x;
    ((float4*)out)[gtid] = make_float4(-1.0f, -1.0f, -1.0f, -1.0f);

    int w    = gtid >> 5;                    // warp id 0..4095
    int lane = threadIdx.x & 31;

    // Warp packs tokens 4w .. 4w+3 (warp-uniform key/query split: 8192 % 4 == 0)
    #pragma unroll
    for (int i = 0; i < 4; ++i) {
        int tg   = 4 * w + i;                // 0..16383
        bool is_q = (tg >= BATCH * LEN);
        int  tok  = is_q ? (tg - BATCH * LEN) : tg;
        const float* p = (is_q ? query_up : key_up) + (size_t)tok * DIM;
        unsigned lo = __ballot_sync(0xFFFFFFFFu, p[lane]      > 0.0f);
        unsigned hi = __ballot_sync(0xFFFFFFFFu, p[lane + 32] > 0.0f);
        if (lane == 0) {
            if (is_q) g_qbits[tok] = make_uint2(lo, hi);
            else      g_keys [tok] = make_uint2(lo, hi);
        }
    }
}

// ---------------------------------------------------------------------------
// K2: one block per batch (4 x 1024), 128 KB dynamic smem byte-Bloom.
// Insert = plain ST.U8 of the constant 1 -- byte-granular stores of the same
// value race harmlessly, so NO atomics (the R13 bottleneck: 12K smem
// atomicOr per block ~= 5.8us). k=3, fill ~9%, FP/query ~1.5e-3 -> ~12
// expected suspects chip-wide; zero false negatives by construction.
// Suspects resolved with the exact ordered ballot scan (R7 semantics),
// overwriting K1's blanket -1s. Non-suspects: blanket already correct.
// ---------------------------------------------------------------------------
__global__ void __launch_bounds__(1024)
verify_kernel(float* __restrict__ out) {
    extern __shared__ unsigned char filt[];  // [2][FBYTES]: lo @0, hi @FBYTES

    int b    = blockIdx.x;
    int t    = threadIdx.x;
    int lane = t & 31;

    // Zero 128 KB: 8192 uint4 / 1024 threads = 8 STS.128 each.
    #pragma unroll
    for (int i = 0; i < 8; ++i)
        ((uint4*)filt)[i * 1024 + t] = make_uint4(0u, 0u, 0u, 0u);
    __syncthreads();

    // Insert this thread's 2 keys (one LDG.128): 12 plain byte stores.
    const uint4* gk4 = (const uint4*)(g_keys + (size_t)b * LEN);
    uint4 kk = gk4[t];
    #define INS(off, w) do {                         \
        filt[(off) + ((w) & 0xFFFFu)] = 1;           \
        filt[(off) + ((w) >> 16)]     = 1;           \
        filt[(off) + hh3(w)]          = 1;           \
    } while (0)
    INS(0,      kk.x);  INS(FBYTES, kk.y);           // key 2t
    INS(0,      kk.z);  INS(FBYTES, kk.w);           // key 2t+1
    #undef INS
    __syncthreads();

    // Probe this thread's 2 queries (one LDG.128): 12 byte loads.
    const uint4* gq4 = (const uint4*)(g_qbits + (size_t)b * LEN);
    uint4 qq = gq4[t];
    #define TEST3(off, w) ( filt[(off) + ((w) & 0xFFFFu)] \
                          & filt[(off) + ((w) >> 16)]     \
                          & filt[(off) + hh3(w)] )
    bool s0 = (TEST3(0, qq.x) | TEST3(FBYTES, qq.y)) != 0;   // query 2t
    bool s1 = (TEST3(0, qq.z) | TEST3(FBYTES, qq.w)) != 0;   // query 2t+1
    #undef TEST3

    unsigned m0 = __ballot_sync(0xFFFFFFFFu, s0);
    unsigned m1 = __ballot_sync(0xFFFFFFFFu, s1);
    if (__builtin_expect((m0 | m1) == 0u, 1)) return;        // certain case

    // ---- RARE PATH: exact ordered ballot scan per suspect query ----
    const uint2* gk = g_keys + (size_t)b * LEN;
    unsigned lt_mask = (1u << lane) - 1u;
    int wbase = (t >> 5) << 6;                               // warp's 1st query

    #pragma unroll
    for (int rep = 0; rep < 2; ++rep) {
        unsigned rem = rep ? m1 : m0;
        while (rem) {
            int l = __ffs((int)rem) - 1;  rem &= rem - 1u;
            unsigned sqlo = __shfl_sync(0xFFFFFFFFu, rep ? qq.z : qq.x, l);
            unsigned sqhi = __shfl_sync(0xFFFFFFFFu, rep ? qq.w : qq.y, l);
            int qid = wbase + 2 * l + rep;                   // batch-local id
            float* so = out + ((size_t)b * LEN + qid) * KMAX;
            int count = 0;
            for (int c = 0; c < LEN / 32; ++c) {
                int j = c * 32 + lane;
                uint2 k = gk[j];
                bool m = (k.x == sqlo) | (k.y == sqhi);
                unsigned mask = __ballot_sync(0xFFFFFFFFu, m);
                if (mask) {
                    int pos = count + __popc(mask & lt_mask);
                    if (m && pos < KMAX) so[pos] = (float)j;
                    count += __popc(mask);
                    if (count >= KMAX) break;                // warp-uniform
                }
            }
            for (int p = count + lane; p < KMAX; p += 32)    // re-pad
                so[p] = -1.0f;
        }
    }
}

// ---------------------------------------------------------------------------
// Launch: inputs = query_up (f32), key_up (f32), head_idx (unused).
// Two graph-capturable launches, no syncs, no allocations.
// ---------------------------------------------------------------------------
extern "C" void kernel_launch(void* const* d_in, const int* in_sizes, int n_in,
                              void* d_out, int out_size) {
    const float* query_up = (const float*)d_in[0];
    const float* key_up   = (const float*)d_in[1];
    float* out = (float*)d_out;

    // Opt-in to 128 KB dynamic smem (idempotent; not an allocation API).
    cudaFuncSetAttribute(verify_kernel,
                         cudaFuncAttributeMaxDynamicSharedMemorySize,
                         FILT_SMEM);

    // Blanket (131072 x float4 = 2 MB) + pack 16384 tokens: 512 blocks.
    pack_blank_kernel<<<512, 256>>>(query_up, key_up, out);
    // One block per batch: byte-Bloom build + probe + rare exact fixup.
    verify_kernel<<<BATCH, 1024, FILT_SMEM>>>(out);
}